// round 6
// baseline (speedup 1.0000x reference)
#include <cuda_runtime.h>

// Dense CRF pairwise loss, B=1, C=2, H=W=96.
// K_ij = 2^(g_i.g_j - h_i - h_j), g = 5-dim scaled feature, h = |g|^2/2.
// Tile-symmetry: sum over a<=b tile pairs, off-diag doubled.
// Per-i weight hoisted: Sum_j k*(A_i+B_i*p_j) = A_i*Sum k + B_i*Sum k*p_j.

#define Hdim   96
#define Wdim   96
#define NPIX   9216
#define TPB    768
#define IPT    2
#define ITILE  1536          // TPB*IPT
#define NTILES 6             // 9216/1536
#define NTPAIR 21            // triangle incl diagonal
#define NCHUNK 14
#define NBLK   (NTPAIR*NCHUNK)  // 294 blocks = 2 per SM (148 SMs)
#define JP_TILE (ITILE/2)    // 768 j-pairs per tile
#define JPMAX  55            // ceil(768/14)

__device__ float g_part[NBLK];
__device__ int   g_cnt = 0;

typedef unsigned long long u64;

__device__ __forceinline__ u64 splat2(float v) {
    u64 r; asm("mov.b64 %0,{%1,%1};" : "=l"(r) : "f"(v)); return r;
}
__device__ __forceinline__ u64 pk2(float a, float b) {
    u64 r; asm("mov.b64 %0,{%1,%2};" : "=l"(r) : "f"(a), "f"(b)); return r;
}
__device__ __forceinline__ void up2(u64 v, float& a, float& b) {
    asm("mov.b64 {%0,%1},%2;" : "=f"(a), "=f"(b) : "l"(v));
}
__device__ __forceinline__ u64 fma2(u64 a, u64 b, u64 c) {
    u64 d; asm("fma.rn.f32x2 %0,%1,%2,%3;" : "=l"(d) : "l"(a), "l"(b), "l"(c)); return d;
}
__device__ __forceinline__ u64 add2(u64 a, u64 b) {
    u64 d; asm("add.rn.f32x2 %0,%1,%2;" : "=l"(d) : "l"(a), "l"(b)); return d;
}
__device__ __forceinline__ float ex2f(float x) {
    float r; asm("ex2.approx.ftz.f32 %0,%1;" : "=f"(r) : "f"(x)); return r;
}

__device__ __forceinline__ void pix_feat(const float* __restrict__ probs,
                                         const float* __restrict__ image, int n,
                                         float& gy, float& gx, float& gr, float& gg,
                                         float& gb, float& nh, float& p) {
    const float SXY  = 0.080074306f;   // sqrt(log2e/225)
    const float SRGB = 9.6083684f;     // sqrt(64*log2e)
    gy = (float)(n / Wdim) * SXY;
    gx = (float)(n % Wdim) * SXY;
    gr = image[n] * SRGB;
    gg = image[NPIX + n] * SRGB;
    gb = image[2 * NPIX + n] * SRGB;
    nh = -0.5f * (gy*gy + gx*gx + gr*gr + gg*gg + gb*gb);
    p  = probs[n];
}

__global__ void __launch_bounds__(TPB, 2) crf_fused(const float* __restrict__ probs,
                                                    const float* __restrict__ image,
                                                    float* __restrict__ out) {
    // j-features packed as f32x2 pairs: LDS.128 reg pairs feed fma.f32x2 directly
    __shared__ ulonglong2 sA[JPMAX];   // {gy01, gx01}
    __shared__ ulonglong2 sB[JPMAX];   // {gr01, gg01}
    __shared__ ulonglong2 sC[JPMAX];   // {gb01, nh01}
    __shared__ u64        sP[JPMAX];   // p01
    __shared__ float      ws[TPB / 32];
    __shared__ bool       isLast;

    const int tid = threadIdx.x;
    const int bid = blockIdx.x;
    const int pairIdx = bid / NCHUNK;
    const int chunk   = bid % NCHUNK;

    int a = 0, b = 0, idx = pairIdx;
    #pragma unroll
    for (int aa = 0; aa < NTILES; ++aa) {
        int cnt = NTILES - aa;
        if (idx < cnt) { a = aa; b = aa + idx; break; }
        idx -= cnt;
    }

    const int jp0 = b * JP_TILE + (chunk * JP_TILE) / NCHUNK;
    const int jp1 = b * JP_TILE + ((chunk + 1) * JP_TILE) / NCHUNK;
    const int nJp = jp1 - jp0;

    if (tid < nJp) {
        int j0 = 2 * (jp0 + tid);
        float gy0, gx0, gr0, gg0, gb0, nh0, p0;
        float gy1, gx1, gr1, gg1, gb1, nh1, p1;
        pix_feat(probs, image, j0,     gy0, gx0, gr0, gg0, gb0, nh0, p0);
        pix_feat(probs, image, j0 + 1, gy1, gx1, gr1, gg1, gb1, nh1, p1);
        sA[tid] = make_ulonglong2(pk2(gy0, gy1), pk2(gx0, gx1));
        sB[tid] = make_ulonglong2(pk2(gr0, gr1), pk2(gg0, gg1));
        sC[tid] = make_ulonglong2(pk2(gb0, gb1), pk2(nh0, nh1));
        sP[tid] = pk2(p0, p1);
    }

    const float wscale = (a == b) ? 1.0f : 2.0f;
    u64 gyi[IPT], gxi[IPT], gri[IPT], ggi[IPT], gbi[IPT], nhi[IPT];
    u64 accA[IPT], accB[IPT];          // Sum k ; Sum k*pj
    float Ai[IPT], Bi[IPT];
    #pragma unroll
    for (int m = 0; m < IPT; ++m) {
        int i = a * ITILE + tid + m * TPB;
        float gy, gx, gr, gg, gb, nh, p;
        pix_feat(probs, image, i, gy, gx, gr, gg, gb, nh, p);
        gyi[m] = splat2(gy); gxi[m] = splat2(gx);
        gri[m] = splat2(gr); ggi[m] = splat2(gg); gbi[m] = splat2(gb);
        nhi[m] = splat2(nh);
        Ai[m] = wscale * p;
        Bi[m] = wscale * (1.0f - 2.0f * p);
        accA[m] = 0ull; accB[m] = 0ull;
    }
    __syncthreads();

    #pragma unroll 2
    for (int jp = 0; jp < nJp; ++jp) {
        ulonglong2 A = sA[jp], B = sB[jp], C = sC[jp];
        u64 pj = sP[jp];
        #pragma unroll
        for (int m = 0; m < IPT; ++m) {
            u64 t = add2(nhi[m], C.y);
            t = fma2(gyi[m], A.x, t);
            t = fma2(gxi[m], A.y, t);
            t = fma2(gri[m], B.x, t);
            t = fma2(ggi[m], B.y, t);
            t = fma2(gbi[m], C.x, t);
            float t0, t1; up2(t, t0, t1);
            u64 k = pk2(ex2f(t0), ex2f(t1));
            accA[m] = add2(accA[m], k);
            accB[m] = fma2(k, pj, accB[m]);
        }
    }

    // apply per-i weights, block reduce (fixed order -> deterministic)
    float s = 0.0f;
    #pragma unroll
    for (int m = 0; m < IPT; ++m) {
        float a0, a1, b0, b1;
        up2(accA[m], a0, a1);
        up2(accB[m], b0, b1);
        s += Ai[m] * (a0 + a1) + Bi[m] * (b0 + b1);
    }
    #pragma unroll
    for (int off = 16; off > 0; off >>= 1)
        s += __shfl_down_sync(0xffffffffu, s, off);
    if ((tid & 31) == 0) ws[tid >> 5] = s;
    __syncthreads();
    if (tid == 0) {
        float t = 0.0f;
        #pragma unroll
        for (int k = 0; k < TPB / 32; ++k) t += ws[k];
        g_part[bid] = t;
        __threadfence();
        int old = atomicAdd(&g_cnt, 1);
        isLast = (old == NBLK - 1);
    }
    __syncthreads();
    if (isLast && tid < 32) {
        __threadfence();
        float acc2 = 0.0f;
        #pragma unroll 4
        for (int k = tid; k < NBLK; k += 32) acc2 += __ldcg(&g_part[k]);
        #pragma unroll
        for (int off = 16; off > 0; off >>= 1)
            acc2 += __shfl_down_sync(0xffffffffu, acc2, off);
        if (tid == 0) {
            out[0] = acc2 * (1.0f / (float)NPIX);
            g_cnt = 0;   // reset for next graph replay
        }
    }
}

extern "C" void kernel_launch(void* const* d_in, const int* in_sizes, int n_in,
                              void* d_out, int out_size) {
    const float* probs = (const float*)d_in[0];
    const float* image = (const float*)d_in[1];
    float* out = (float*)d_out;
    crf_fused<<<NBLK, TPB>>>(probs, image, out);
}

// round 7
// speedup vs baseline: 1.0499x; 1.0499x over previous
#include <cuda_runtime.h>

// Dense CRF pairwise loss, B=1, C=2, H=W=96.
// K_ij = 2^(-c_xy*dxy - c_rgb*drgb). Factor the Delta-y part per row pair:
//   K_ij = 2^(-CY*(y_i-y_j)^2) * 2^(g_i.g_j + nh_i + nh_j),  g = (gx,gr,gg,gb) 4-dim.
// j-loop runs row-by-row; the row factor multiplies the per-row accumulators.
// Tile-symmetry: sum over a<=b tile pairs, off-diag doubled.
// Per-i weight hoisted: Sum_j k*(A_i+B_i*p_j) = A_i*Sum k + B_i*Sum k*p_j.

#define Wdim   96
#define NPIX   9216
#define RPT    12            // rows per tile
#define ITILE  1152          // RPT*Wdim
#define NTILES 8
#define NTPAIR 36            // triangle incl diagonal
#define RPC    3             // j-rows per chunk
#define NCHUNK 4             // chunks per j-tile
#define NBLK   (NTPAIR*NCHUNK)  // 144 blocks = 1 wave
#define TPB    576
#define IPT    2
#define JP_ROW 48            // j-pairs per row
#define JP_CHUNK (RPC*JP_ROW)   // 144

__device__ float g_part[NBLK];
__device__ int   g_cnt = 0;

typedef unsigned long long u64;

__device__ __forceinline__ u64 splat2(float v) {
    u64 r; asm("mov.b64 %0,{%1,%1};" : "=l"(r) : "f"(v)); return r;
}
__device__ __forceinline__ u64 pk2(float a, float b) {
    u64 r; asm("mov.b64 %0,{%1,%2};" : "=l"(r) : "f"(a), "f"(b)); return r;
}
__device__ __forceinline__ void up2(u64 v, float& a, float& b) {
    asm("mov.b64 {%0,%1},%2;" : "=f"(a), "=f"(b) : "l"(v));
}
__device__ __forceinline__ u64 fma2(u64 a, u64 b, u64 c) {
    u64 d; asm("fma.rn.f32x2 %0,%1,%2,%3;" : "=l"(d) : "l"(a), "l"(b), "l"(c)); return d;
}
__device__ __forceinline__ u64 add2(u64 a, u64 b) {
    u64 d; asm("add.rn.f32x2 %0,%1,%2;" : "=l"(d) : "l"(a), "l"(b)); return d;
}
__device__ __forceinline__ float ex2f(float x) {
    float r; asm("ex2.approx.ftz.f32 %0,%1;" : "=f"(r) : "f"(x)); return r;
}

// 4-dim feature (x,rgb): gx,gr,gg,gb scaled; nh = -|g4|^2/2; p class-0 prob
__device__ __forceinline__ void pix_feat4(const float* __restrict__ probs,
                                          const float* __restrict__ image, int n,
                                          float& gx, float& gr, float& gg,
                                          float& gb, float& nh, float& p) {
    const float SXY  = 0.080074306f;   // sqrt(log2e/225)
    const float SRGB = 9.6083684f;     // sqrt(64*log2e)
    gx = (float)(n % Wdim) * SXY;
    gr = image[n] * SRGB;
    gg = image[NPIX + n] * SRGB;
    gb = image[2 * NPIX + n] * SRGB;
    nh = -0.5f * (gx*gx + gr*gr + gg*gg + gb*gb);
    p  = probs[n];
}

__global__ void __launch_bounds__(TPB) crf_fused(const float* __restrict__ probs,
                                                 const float* __restrict__ image,
                                                 float* __restrict__ out) {
    // j-features packed as f32x2 pairs: LDS.128 reg pairs feed fma.f32x2 directly
    __shared__ ulonglong2 sD[JP_CHUNK];   // {gx01, gr01}
    __shared__ ulonglong2 sE[JP_CHUNK];   // {gg01, gb01}
    __shared__ ulonglong2 sF[JP_CHUNK];   // {nh01, p01}
    __shared__ float      ws[TPB / 32];
    __shared__ bool       isLast;

    const int tid = threadIdx.x;
    const int bid = blockIdx.x;
    const int pairIdx = bid / NCHUNK;
    const int chunk   = bid % NCHUNK;

    int a = 0, b = 0, idx = pairIdx;
    #pragma unroll
    for (int aa = 0; aa < NTILES; ++aa) {
        int cnt = NTILES - aa;
        if (idx < cnt) { a = aa; b = aa + idx; break; }
        idx -= cnt;
    }

    const int jrow0 = b * RPT + chunk * RPC;     // first j image-row of this chunk
    const int jbase = jrow0 * Wdim;

    if (tid < JP_CHUNK) {
        int j0 = jbase + 2 * tid;
        float gx0, gr0, gg0, gb0, nh0, p0;
        float gx1, gr1, gg1, gb1, nh1, p1;
        pix_feat4(probs, image, j0,     gx0, gr0, gg0, gb0, nh0, p0);
        pix_feat4(probs, image, j0 + 1, gx1, gr1, gg1, gb1, nh1, p1);
        sD[tid] = make_ulonglong2(pk2(gx0, gx1), pk2(gr0, gr1));
        sE[tid] = make_ulonglong2(pk2(gg0, gg1), pk2(gb0, gb1));
        sF[tid] = make_ulonglong2(pk2(nh0, nh1), pk2(p0, p1));
    }

    const float wscale = (a == b) ? 1.0f : 2.0f;
    u64 gxi[IPT], gri[IPT], ggi[IPT], gbi[IPT], nhi[IPT];
    u64 accA[IPT], accB[IPT];          // Sum rowfac*Sum_row k ; same for k*pj
    float Ai[IPT], Bi[IPT], yi[IPT];
    #pragma unroll
    for (int m = 0; m < IPT; ++m) {
        int i = a * ITILE + tid + m * TPB;
        float gx, gr, gg, gb, nh, p;
        pix_feat4(probs, image, i, gx, gr, gg, gb, nh, p);
        gxi[m] = splat2(gx);
        gri[m] = splat2(gr); ggi[m] = splat2(gg); gbi[m] = splat2(gb);
        nhi[m] = splat2(nh);
        yi[m]  = (float)(i / Wdim);
        Ai[m] = wscale * p;
        Bi[m] = wscale * (1.0f - 2.0f * p);
        accA[m] = 0ull; accB[m] = 0ull;
    }
    __syncthreads();

    const float CY = 0.0032059890f;    // log2e / (2*15^2)
    #pragma unroll
    for (int r = 0; r < RPC; ++r) {
        // per-row y factor: 2^(-CY*(y_i - y_j)^2), y_j constant over the row
        u64 rowfac[IPT];
        u64 rA[IPT], rB[IPT];
        const float yj = (float)(jrow0 + r);
        #pragma unroll
        for (int m = 0; m < IPT; ++m) {
            float dy = yi[m] - yj;
            rowfac[m] = splat2(ex2f(-CY * dy * dy));
            rA[m] = 0ull; rB[m] = 0ull;
        }
        const int jpEnd = (r + 1) * JP_ROW;
        #pragma unroll 2
        for (int jp = r * JP_ROW; jp < jpEnd; ++jp) {
            ulonglong2 D = sD[jp], E = sE[jp], F = sF[jp];
            #pragma unroll
            for (int m = 0; m < IPT; ++m) {
                u64 t = add2(nhi[m], F.x);
                t = fma2(gxi[m], D.x, t);
                t = fma2(gri[m], D.y, t);
                t = fma2(ggi[m], E.x, t);
                t = fma2(gbi[m], E.y, t);
                float t0, t1; up2(t, t0, t1);
                u64 k = pk2(ex2f(t0), ex2f(t1));
                rA[m] = add2(rA[m], k);
                rB[m] = fma2(k, F.y, rB[m]);
            }
        }
        #pragma unroll
        for (int m = 0; m < IPT; ++m) {
            accA[m] = fma2(rowfac[m], rA[m], accA[m]);
            accB[m] = fma2(rowfac[m], rB[m], accB[m]);
        }
    }

    // apply per-i weights, block reduce (fixed order -> deterministic)
    float s = 0.0f;
    #pragma unroll
    for (int m = 0; m < IPT; ++m) {
        float a0, a1, b0, b1;
        up2(accA[m], a0, a1);
        up2(accB[m], b0, b1);
        s += Ai[m] * (a0 + a1) + Bi[m] * (b0 + b1);
    }
    #pragma unroll
    for (int off = 16; off > 0; off >>= 1)
        s += __shfl_down_sync(0xffffffffu, s, off);
    if ((tid & 31) == 0) ws[tid >> 5] = s;
    __syncthreads();
    if (tid == 0) {
        float t = 0.0f;
        #pragma unroll
        for (int k = 0; k < TPB / 32; ++k) t += ws[k];
        g_part[bid] = t;
        __threadfence();
        int old = atomicAdd(&g_cnt, 1);
        isLast = (old == NBLK - 1);
    }
    __syncthreads();
    if (isLast && tid < 32) {
        __threadfence();
        float acc2 = 0.0f;
        #pragma unroll
        for (int k = tid; k < NBLK; k += 32) acc2 += __ldcg(&g_part[k]);
        #pragma unroll
        for (int off = 16; off > 0; off >>= 1)
            acc2 += __shfl_down_sync(0xffffffffu, acc2, off);
        if (tid == 0) {
            out[0] = acc2 * (1.0f / (float)NPIX);
            g_cnt = 0;   // reset for next graph replay
        }
    }
}

extern "C" void kernel_launch(void* const* d_in, const int* in_sizes, int n_in,
                              void* d_out, int out_size) {
    const float* probs = (const float*)d_in[0];
    const float* image = (const float*)d_in[1];
    float* out = (float*)d_out;
    crf_fused<<<NBLK, TPB>>>(probs, image, out);
}